// round 1
// baseline (speedup 1.0000x reference)
#include <cuda_runtime.h>
#include <math.h>

#define BB 4
#define CC 128
#define NBOX 4
#define BTC 32
#define HH 256
#define WW 256
#define HWSZ (HH*WW)

// scratch (static device globals; no dynamic allocation)
__device__ float g_z[BB*BTC*HH*WW];            // BN1(conv1x1(x))   : 33.5 MB
__device__ float g_Ccol[BB*BTC*(HH+1)*WW];     // column cumsum of z: 33.7 MB

// ---------------------------------------------------------------------------
// Kernel 1: z = BN1(x @ w1^T), one thread per pixel, all 32 output channels
// ---------------------------------------------------------------------------
__global__ __launch_bounds__(256) void k1_conv_bn(
    const float* __restrict__ x, const float* __restrict__ w1,
    const float* __restrict__ g1, const float* __restrict__ b1,
    const float* __restrict__ m1, const float* __restrict__ v1)
{
    __shared__ float ws[CC*BTC];      // ws[c*32 + k] = w1[k*128 + c]
    __shared__ float inv1[BTC], bias1[BTC];
    const int tid = threadIdx.x;

    for (int idx = tid; idx < CC*BTC; idx += blockDim.x) {
        int k = idx & 31;
        int c = idx >> 5;
        ws[idx] = w1[k*CC + c];
    }
    if (tid < BTC) {
        float inv = g1[tid] * rsqrtf(v1[tid] + 1e-5f);
        inv1[tid]  = inv;
        bias1[tid] = b1[tid] - m1[tid]*inv;
    }
    __syncthreads();

    const int pix = blockIdx.x * 256 + tid;     // over B*H*W = 262144 exactly
    const int b   = pix >> 16;                  // HW = 65536
    const int ij  = pix & 65535;
    const float* xp = x + (size_t)b*CC*HWSZ + ij;

    float acc[BTC];
    #pragma unroll
    for (int k = 0; k < BTC; k++) acc[k] = 0.f;

    #pragma unroll 4
    for (int c = 0; c < CC; c++) {
        float xv = xp[(size_t)c*HWSZ];
        const float4* wv = (const float4*)(ws + c*BTC);
        #pragma unroll
        for (int q = 0; q < 8; q++) {
            float4 w4 = wv[q];
            acc[4*q+0] += xv*w4.x;
            acc[4*q+1] += xv*w4.y;
            acc[4*q+2] += xv*w4.z;
            acc[4*q+3] += xv*w4.w;
        }
    }

    float* zp = g_z + (size_t)b*BTC*HWSZ + ij;
    #pragma unroll
    for (int k = 0; k < BTC; k++)
        zp[(size_t)k*HWSZ] = acc[k]*inv1[k] + bias1[k];
}

// ---------------------------------------------------------------------------
// Kernel 2: column cumsum with a leading zero row:
//   Ccol[plane][0][j]   = 0
//   Ccol[plane][i+1][j] = sum_{p<=i} z[plane][p][j]
// one thread per column, coalesced across j
// ---------------------------------------------------------------------------
__global__ __launch_bounds__(256) void k2_colsum()
{
    const int plane = blockIdx.x;    // b*32+bt, 128 planes
    const int j     = threadIdx.x;
    const float* zp = g_z    + (size_t)plane*HWSZ + j;
    float*       Cp = g_Ccol + (size_t)plane*(HH+1)*WW + j;
    float acc = 0.f;
    Cp[0] = 0.f;
    #pragma unroll 4
    for (int i = 0; i < HH; i++) {
        acc += zp[(size_t)i*WW];
        Cp[(size_t)(i+1)*WW] = acc;
    }
}

// ---------------------------------------------------------------------------
// Kernel 3: separable fractional box filter + BN2 + ReLU + residual ReLU
// one block per output row (b, bt, nb, i); 256 threads = columns
// ---------------------------------------------------------------------------
__global__ __launch_bounds__(256) void k3_box(
    const float* __restrict__ x,
    const float* __restrict__ xmn_, const float* __restrict__ xmx_,
    const float* __restrict__ ymn_, const float* __restrict__ ymx_,
    const float* __restrict__ g2, const float* __restrict__ b2,
    const float* __restrict__ m2, const float* __restrict__ v2,
    float* __restrict__ out)
{
    __shared__ float P[WW+1];
    __shared__ float wsum[8];

    const int bid = blockIdx.x;
    const int i   = bid & (HH-1);
    const int nb  = (bid >> 8) & (NBOX-1);
    const int bt  = (bid >> 10) & (BTC-1);
    const int b   = bid >> 15;
    const int j   = threadIdx.x;
    const int k   = bt*NBOX + nb;              // output channel 0..127
    const int boxi = bt*NBOX + nb;             // (BT,NB) flattened

    const float xmn = xmn_[boxi], xmx = xmx_[boxi];
    const float ymn = ymn_[boxi], ymx = ymx_[boxi];

    // vertical sample rows: constant over the whole block
    float uA = fminf(fmaxf((float)i + xmx, 0.f), 256.f);
    float uB = fminf(fmaxf((float)i + xmn, 0.f), 256.f);
    float fA = fminf(floorf(uA), 255.f);
    float fB = fminf(floorf(uB), 255.f);
    int   iA = (int)fA, iB = (int)fB;
    float wA = uA - fA, wB = uB - fB;

    const float* Cp = g_Ccol + (size_t)(b*BTC + bt)*(HH+1)*WW;
    // fractional vertical box sum at column j
    float v = (Cp[(size_t)iA*WW + j]*(1.f - wA) + Cp[(size_t)(iA+1)*WW + j]*wA)
            - (Cp[(size_t)iB*WW + j]*(1.f - wB) + Cp[(size_t)(iB+1)*WW + j]*wB);

    // ---- block-wide inclusive scan of v over j (8 warps) ----
    const int lane = j & 31, warp = j >> 5;
    float s = v;
    #pragma unroll
    for (int o = 1; o < 32; o <<= 1) {
        float t = __shfl_up_sync(0xffffffffu, s, o);
        if (lane >= o) s += t;
    }
    if (lane == 31) wsum[warp] = s;
    __syncthreads();
    if (warp == 0) {
        float t = (lane < 8) ? wsum[lane] : 0.f;
        #pragma unroll
        for (int o = 1; o < 8; o <<= 1) {
            float u = __shfl_up_sync(0xffffffffu, t, o);
            if (lane >= o) t += u;
        }
        if (lane < 8) wsum[lane] = t;
    }
    __syncthreads();
    float incl = s + ((warp > 0) ? wsum[warp-1] : 0.f);
    if (j == 0) P[0] = 0.f;
    P[j+1] = incl;
    __syncthreads();

    // ---- horizontal fractional box via P ----
    float vA = fminf(fmaxf((float)j + ymx, 0.f), 256.f);
    float vB = fminf(fmaxf((float)j + ymn, 0.f), 256.f);
    float gA = fminf(floorf(vA), 255.f);
    float gB = fminf(floorf(vB), 255.f);
    int jA = (int)gA, jB = (int)gB;
    float wvA = vA - gA, wvB = vB - gB;

    float PA = P[jA]*(1.f - wvA) + P[jA+1]*wvA;
    float PB = P[jB]*(1.f - wvB) + P[jB+1]*wvB;
    float area = (xmx - xmn) * (ymx - ymn);
    float val = (PA - PB) / area;

    // BN2 + relu + residual relu
    float inv  = g2[k] * rsqrtf(v2[k] + 1e-3f);
    val = val*inv + (b2[k] - m2[k]*inv);
    val = fmaxf(val, 0.f);

    size_t oidx = ((size_t)(b*CC + k)*HH + i)*WW + j;
    out[oidx] = fmaxf(x[oidx] + val, 0.f);
}

// ---------------------------------------------------------------------------
extern "C" void kernel_launch(void* const* d_in, const int* in_sizes, int n_in,
                              void* d_out, int out_size)
{
    const float* x    = (const float*)d_in[0];
    const float* w1   = (const float*)d_in[1];
    const float* g1   = (const float*)d_in[2];
    const float* b1   = (const float*)d_in[3];
    const float* m1   = (const float*)d_in[4];
    const float* v1   = (const float*)d_in[5];
    const float* xmn  = (const float*)d_in[6];
    const float* xmx  = (const float*)d_in[7];
    const float* ymn  = (const float*)d_in[8];
    const float* ymx  = (const float*)d_in[9];
    const float* g2   = (const float*)d_in[10];
    const float* b2   = (const float*)d_in[11];
    const float* m2   = (const float*)d_in[12];
    const float* v2   = (const float*)d_in[13];
    float* out = (float*)d_out;

    k1_conv_bn<<<(BB*HWSZ)/256, 256>>>(x, w1, g1, b1, m1, v1);
    k2_colsum<<<BB*BTC, 256>>>();
    k3_box<<<BB*BTC*NBOX*HH, 256>>>(x, xmn, xmx, ymn, ymx, g2, b2, m2, v2, out);
}

// round 2
// speedup vs baseline: 1.8878x; 1.8878x over previous
#include <cuda_runtime.h>
#include <math.h>

#define BB 4
#define CC 128
#define NBOX 4
#define BTC 32
#define HH 256
#define WW 256
#define HWSZ (HH*WW)
#define SW 257                      // integral image row width (H+1 = W+1 = 257)

// scratch (static device globals; no dynamic allocation)
__device__ float g_z[BB*BTC*HH*WW];       // z = BN1(conv); column-cumsum'd IN PLACE
__device__ float g_S[BB*BTC*SW*SW];       // full 2D integral image, zero borders

// ---------------------------------------------------------------------------
// Kernel 1: z = BN1(x @ w1^T)  — register-tiled GEMM
// tile: 256 pixels x 32 channels, K=128 in 4 chunks of 32
// thread: 4 pixels x 8 channels = 32 accumulators
// BN1 scale folded into weights; bias added in epilogue.
// ---------------------------------------------------------------------------
__global__ __launch_bounds__(256) void k1_conv_bn(
    const float* __restrict__ x, const float* __restrict__ w1,
    const float* __restrict__ g1, const float* __restrict__ b1,
    const float* __restrict__ m1, const float* __restrict__ v1)
{
    __shared__ float xs[32][256];    // x chunk: 32 channels x 256 pixels (32KB)
    __shared__ float ws[128][32];    // ws[c][k] = w1[k][c] * inv1[k]     (16KB)

    const int tid = threadIdx.x;

    // load weights, folding BN1 scale
    for (int idx = tid; idx < CC*BTC; idx += 256) {
        int k = idx & 31;
        int c = idx >> 5;
        float inv = g1[k] * rsqrtf(v1[k] + 1e-5f);
        ws[c][k] = w1[k*CC + c] * inv;
    }

    const int pixbase = blockIdx.x * 256;
    const int b  = pixbase >> 16;
    const int ij = pixbase & 65535;
    const float* xp = x + (size_t)b*CC*HWSZ + ij;

    const int tp = tid & 63;         // pixel group: px = tp*4 .. tp*4+3
    const int tk = tid >> 6;         // channel group: k = tk*8 .. tk*8+7

    float acc[4][8];
    #pragma unroll
    for (int p = 0; p < 4; p++)
        #pragma unroll
        for (int q = 0; q < 8; q++) acc[p][q] = 0.f;

    const int cl = tid >> 6;         // staging: channel lane 0..3
    const int p4 = (tid & 63) * 4;   // staging: pixel offset

    for (int kc = 0; kc < CC; kc += 32) {
        __syncthreads();             // protect xs (and ws on first iter)
        // stage x chunk: 32 channels x 256 px, coalesced float4
        #pragma unroll
        for (int it = 0; it < 8; it++) {
            int c = kc + it*4 + cl;
            float4 v = *(const float4*)(xp + (size_t)c*HWSZ + p4);
            *(float4*)&xs[it*4 + cl][p4] = v;
        }
        __syncthreads();

        #pragma unroll
        for (int c = 0; c < 32; c++) {
            float4 xv = *(float4*)&xs[c][tp*4];
            float4 wa = *(float4*)&ws[kc + c][tk*8];
            float4 wb = *(float4*)&ws[kc + c][tk*8 + 4];
            float xr[4] = {xv.x, xv.y, xv.z, xv.w};
            float wr[8] = {wa.x, wa.y, wa.z, wa.w, wb.x, wb.y, wb.z, wb.w};
            #pragma unroll
            for (int p = 0; p < 4; p++)
                #pragma unroll
                for (int q = 0; q < 8; q++)
                    acc[p][q] += xr[p] * wr[q];
        }
    }

    // epilogue: add BN1 bias, write z
    #pragma unroll
    for (int q = 0; q < 8; q++) {
        int k = tk*8 + q;
        float inv  = g1[k] * rsqrtf(v1[k] + 1e-5f);
        float bias = b1[k] - m1[k]*inv;
        float4 r = make_float4(acc[0][q] + bias, acc[1][q] + bias,
                               acc[2][q] + bias, acc[3][q] + bias);
        *(float4*)(g_z + (size_t)(b*BTC + k)*HWSZ + ij + tp*4) = r;
    }
}

// ---------------------------------------------------------------------------
// Kernel 2a: column cumsum IN PLACE on g_z, chunked over rows (4 chunks of 64)
// Each chunk holds a LOCAL cumsum; k2b stitches chunk offsets.
// ---------------------------------------------------------------------------
__global__ __launch_bounds__(256) void k2a_colsum()
{
    const int plane = blockIdx.y;           // 0..127
    const int chunk = blockIdx.x;           // 0..3
    const int j     = threadIdx.x;
    float* zp = g_z + (size_t)plane*HWSZ + (size_t)(chunk*64)*WW + j;
    float acc = 0.f;
    #pragma unroll 8
    for (int r = 0; r < 64; r++) {
        acc += zp[(size_t)r*WW];
        zp[(size_t)r*WW] = acc;
    }
}

// ---------------------------------------------------------------------------
// Kernel 2b: build S row i (0..256): stitch column offsets, then row prefix-scan.
// S[plane][i][0] = 0; S[plane][0][:] = 0.
// ---------------------------------------------------------------------------
__global__ __launch_bounds__(256) void k2b_rowscan()
{
    __shared__ float wsum[8];
    const int plane = blockIdx.x / SW;
    const int i     = blockIdx.x % SW;      // 0..256
    const int j     = threadIdx.x;

    float v = 0.f;
    if (i > 0) {
        const float* zp = g_z + (size_t)plane*HWSZ + j;
        int r = i - 1;
        int q = r >> 6;
        v = zp[(size_t)r*WW];
        for (int p = 0; p < q; p++)
            v += zp[(size_t)(p*64 + 63)*WW];
    }

    // block inclusive scan over j
    const int lane = j & 31, warp = j >> 5;
    float s = v;
    #pragma unroll
    for (int o = 1; o < 32; o <<= 1) {
        float t = __shfl_up_sync(0xffffffffu, s, o);
        if (lane >= o) s += t;
    }
    if (lane == 31) wsum[warp] = s;
    __syncthreads();
    if (warp == 0) {
        float t = (lane < 8) ? wsum[lane] : 0.f;
        #pragma unroll
        for (int o = 1; o < 8; o <<= 1) {
            float u = __shfl_up_sync(0xffffffffu, t, o);
            if (lane >= o) t += u;
        }
        if (lane < 8) wsum[lane] = t;
    }
    __syncthreads();
    float incl = s + ((warp > 0) ? wsum[warp-1] : 0.f);

    float* Sr = g_S + (size_t)plane*SW*SW + (size_t)i*SW;
    if (j == 0) Sr[0] = 0.f;
    Sr[j+1] = incl;
}

// ---------------------------------------------------------------------------
// Kernel 3: box filter via 16 bilinear integral-image taps + BN2 + ReLU + residual
// block = (b, bt, nb, 8-row chunk); thread = column j; no syncthreads.
// ---------------------------------------------------------------------------
__global__ __launch_bounds__(256) void k3_box(
    const float* __restrict__ x,
    const float* __restrict__ xmn_, const float* __restrict__ xmx_,
    const float* __restrict__ ymn_, const float* __restrict__ ymx_,
    const float* __restrict__ g2, const float* __restrict__ b2,
    const float* __restrict__ m2, const float* __restrict__ v2,
    float* __restrict__ out)
{
    const int bid = blockIdx.x;
    const int rc  = bid & 31;                 // row chunk (8 rows)
    const int nb  = (bid >> 5) & (NBOX-1);
    const int bt  = (bid >> 7) & (BTC-1);
    const int b   = bid >> 12;
    const int j   = threadIdx.x;
    const int k   = bt*NBOX + nb;             // output channel
    const int boxi = bt*NBOX + nb;

    const float xmn = xmn_[boxi], xmx = xmx_[boxi];
    const float ymn = ymn_[boxi], ymx = ymx_[boxi];
    const float inv_area = 1.f / ((xmx - xmn) * (ymx - ymn));

    // horizontal sample columns: fixed per thread
    float vA = fminf(fmaxf((float)j + ymx, 0.f), 256.f);
    float vB = fminf(fmaxf((float)j + ymn, 0.f), 256.f);
    float gA = fminf(floorf(vA), 255.f);
    float gB = fminf(floorf(vB), 255.f);
    int   jA = (int)gA, jB = (int)gB;
    float wvA = vA - gA, wvB = vB - gB;

    const float* Sp = g_S + (size_t)(b*BTC + bt)*SW*SW;

    float inv2  = g2[k] * rsqrtf(v2[k] + 1e-3f);
    float bias2 = b2[k] - m2[k]*inv2;

    const float* xrow = x   + ((size_t)(b*CC + k)*HH + rc*8)*WW + j;
    float*       orow = out + ((size_t)(b*CC + k)*HH + rc*8)*WW + j;

    #pragma unroll
    for (int r = 0; r < 8; r++) {
        int i = rc*8 + r;
        float uA = fminf(fmaxf((float)i + xmx, 0.f), 256.f);
        float uB = fminf(fmaxf((float)i + xmn, 0.f), 256.f);
        float fA = fminf(floorf(uA), 255.f);
        float fB = fminf(floorf(uB), 255.f);
        int   iA = (int)fA, iB = (int)fB;
        float wA = uA - fA, wB = uB - fB;

        const float* RA0 = Sp + (size_t)iA*SW;
        const float* RA1 = RA0 + SW;
        const float* RB0 = Sp + (size_t)iB*SW;
        const float* RB1 = RB0 + SW;

        // D(col) = rowlerp_A(col) - rowlerp_B(col)
        float D_A0 = (RA0[jA]  *(1.f-wA) + RA1[jA]  *wA) - (RB0[jA]  *(1.f-wB) + RB1[jA]  *wB);
        float D_A1 = (RA0[jA+1]*(1.f-wA) + RA1[jA+1]*wA) - (RB0[jA+1]*(1.f-wB) + RB1[jA+1]*wB);
        float D_B0 = (RA0[jB]  *(1.f-wA) + RA1[jB]  *wA) - (RB0[jB]  *(1.f-wB) + RB1[jB]  *wB);
        float D_B1 = (RA0[jB+1]*(1.f-wA) + RA1[jB+1]*wA) - (RB0[jB+1]*(1.f-wB) + RB1[jB+1]*wB);

        float DA = D_A0*(1.f - wvA) + D_A1*wvA;
        float DB = D_B0*(1.f - wvB) + D_B1*wvB;
        float val = (DA - DB) * inv_area;

        val = fmaxf(val*inv2 + bias2, 0.f);
        orow[(size_t)r*WW] = fmaxf(xrow[(size_t)r*WW] + val, 0.f);
    }
}

// ---------------------------------------------------------------------------
extern "C" void kernel_launch(void* const* d_in, const int* in_sizes, int n_in,
                              void* d_out, int out_size)
{
    const float* x    = (const float*)d_in[0];
    const float* w1   = (const float*)d_in[1];
    const float* g1   = (const float*)d_in[2];
    const float* b1   = (const float*)d_in[3];
    const float* m1   = (const float*)d_in[4];
    const float* v1   = (const float*)d_in[5];
    const float* xmn  = (const float*)d_in[6];
    const float* xmx  = (const float*)d_in[7];
    const float* ymn  = (const float*)d_in[8];
    const float* ymx  = (const float*)d_in[9];
    const float* g2   = (const float*)d_in[10];
    const float* b2   = (const float*)d_in[11];
    const float* m2   = (const float*)d_in[12];
    const float* v2   = (const float*)d_in[13];
    float* out = (float*)d_out;

    k1_conv_bn<<<(BB*HWSZ)/256, 256>>>(x, w1, g1, b1, m1, v1);
    k2a_colsum<<<dim3(4, BB*BTC), 256>>>();
    k2b_rowscan<<<BB*BTC*SW, 256>>>();
    k3_box<<<BB*BTC*NBOX*(HH/8), 256>>>(x, xmn, xmx, ymn, ymx, g2, b2, m2, v2, out);
}

// round 3
// speedup vs baseline: 2.0530x; 1.0875x over previous
#include <cuda_runtime.h>
#include <math.h>

#define BB 4
#define CC 128
#define NBOX 4
#define BTC 32
#define HH 256
#define WW 256
#define HWSZ (HH*WW)
#define SW 257                      // integral image row width (H+1 = W+1 = 257)

// scratch (static device globals; no dynamic allocation)
__device__ float g_z[BB*BTC*HH*WW];       // z = BN1(conv); column-cumsum'd IN PLACE
__device__ float g_S[BB*BTC*SW*SW];       // full 2D integral image, zero borders

// ---------------------------------------------------------------------------
// Kernel 1: z = BN1(x @ w1^T)  — register-tiled GEMM
// tile: 256 pixels x 32 channels, K=128 in 4 chunks of 32
// thread: 4 pixels x 8 channels = 32 accumulators
// BN1 scale folded into weights; bias added in epilogue.
// ---------------------------------------------------------------------------
__global__ __launch_bounds__(256) void k1_conv_bn(
    const float* __restrict__ x, const float* __restrict__ w1,
    const float* __restrict__ g1, const float* __restrict__ b1,
    const float* __restrict__ m1, const float* __restrict__ v1)
{
    __shared__ float xs[32][256];    // x chunk: 32 channels x 256 pixels (32KB)
    __shared__ float ws[128][32];    // ws[c][k] = w1[k][c] * inv1[k]     (16KB)

    const int tid = threadIdx.x;

    // load weights, folding BN1 scale
    for (int idx = tid; idx < CC*BTC; idx += 256) {
        int k = idx & 31;
        int c = idx >> 5;
        float inv = g1[k] * rsqrtf(v1[k] + 1e-5f);
        ws[c][k] = w1[k*CC + c] * inv;
    }

    const int pixbase = blockIdx.x * 256;
    const int b  = pixbase >> 16;
    const int ij = pixbase & 65535;
    const float* xp = x + (size_t)b*CC*HWSZ + ij;

    const int tp = tid & 63;         // pixel group: px = tp*4 .. tp*4+3
    const int tk = tid >> 6;         // channel group: k = tk*8 .. tk*8+7

    float acc[4][8];
    #pragma unroll
    for (int p = 0; p < 4; p++)
        #pragma unroll
        for (int q = 0; q < 8; q++) acc[p][q] = 0.f;

    const int cl = tid >> 6;         // staging: channel lane 0..3
    const int p4 = (tid & 63) * 4;   // staging: pixel offset

    for (int kc = 0; kc < CC; kc += 32) {
        __syncthreads();             // protect xs (and ws on first iter)
        // stage x chunk: 32 channels x 256 px, coalesced float4
        #pragma unroll
        for (int it = 0; it < 8; it++) {
            int c = kc + it*4 + cl;
            float4 v = *(const float4*)(xp + (size_t)c*HWSZ + p4);
            *(float4*)&xs[it*4 + cl][p4] = v;
        }
        __syncthreads();

        #pragma unroll
        for (int c = 0; c < 32; c++) {
            float4 xv = *(float4*)&xs[c][tp*4];
            float4 wa = *(float4*)&ws[kc + c][tk*8];
            float4 wb = *(float4*)&ws[kc + c][tk*8 + 4];
            float xr[4] = {xv.x, xv.y, xv.z, xv.w};
            float wr[8] = {wa.x, wa.y, wa.z, wa.w, wb.x, wb.y, wb.z, wb.w};
            #pragma unroll
            for (int p = 0; p < 4; p++)
                #pragma unroll
                for (int q = 0; q < 8; q++)
                    acc[p][q] += xr[p] * wr[q];
        }
    }

    // epilogue: add BN1 bias, write z
    #pragma unroll
    for (int q = 0; q < 8; q++) {
        int k = tk*8 + q;
        float inv  = g1[k] * rsqrtf(v1[k] + 1e-5f);
        float bias = b1[k] - m1[k]*inv;
        float4 r = make_float4(acc[0][q] + bias, acc[1][q] + bias,
                               acc[2][q] + bias, acc[3][q] + bias);
        *(float4*)(g_z + (size_t)(b*BTC + k)*HWSZ + ij + tp*4) = r;
    }
}

// ---------------------------------------------------------------------------
// Kernel 2a: column cumsum IN PLACE on g_z, chunked over rows (4 chunks of 64)
// Each chunk holds a LOCAL cumsum; k2b stitches chunk offsets.
// ---------------------------------------------------------------------------
__global__ __launch_bounds__(256) void k2a_colsum()
{
    const int plane = blockIdx.y;           // 0..127
    const int chunk = blockIdx.x;           // 0..3
    const int j     = threadIdx.x;
    float* zp = g_z + (size_t)plane*HWSZ + (size_t)(chunk*64)*WW + j;
    float acc = 0.f;
    #pragma unroll 8
    for (int r = 0; r < 64; r++) {
        acc += zp[(size_t)r*WW];
        zp[(size_t)r*WW] = acc;
    }
}

// ---------------------------------------------------------------------------
// Kernel 2b: build S row i (0..256): stitch column offsets, then row prefix-scan.
// S[plane][i][0] = 0; S[plane][0][:] = 0.
// ---------------------------------------------------------------------------
__global__ __launch_bounds__(256) void k2b_rowscan()
{
    __shared__ float wsum[8];
    const int plane = blockIdx.x / SW;
    const int i     = blockIdx.x % SW;      // 0..256
    const int j     = threadIdx.x;

    float v = 0.f;
    if (i > 0) {
        const float* zp = g_z + (size_t)plane*HWSZ + j;
        int r = i - 1;
        int q = r >> 6;
        v = zp[(size_t)r*WW];
        for (int p = 0; p < q; p++)
            v += zp[(size_t)(p*64 + 63)*WW];
    }

    // block inclusive scan over j
    const int lane = j & 31, warp = j >> 5;
    float s = v;
    #pragma unroll
    for (int o = 1; o < 32; o <<= 1) {
        float t = __shfl_up_sync(0xffffffffu, s, o);
        if (lane >= o) s += t;
    }
    if (lane == 31) wsum[warp] = s;
    __syncthreads();
    if (warp == 0) {
        float t = (lane < 8) ? wsum[lane] : 0.f;
        #pragma unroll
        for (int o = 1; o < 8; o <<= 1) {
            float u = __shfl_up_sync(0xffffffffu, t, o);
            if (lane >= o) t += u;
        }
        if (lane < 8) wsum[lane] = t;
    }
    __syncthreads();
    float incl = s + ((warp > 0) ? wsum[warp-1] : 0.f);

    float* Sr = g_S + (size_t)plane*SW*SW + (size_t)i*SW;
    if (j == 0) Sr[0] = 0.f;
    Sr[j+1] = incl;
}

// ---------------------------------------------------------------------------
// Kernel 3: separable box filter via shared vertical-difference vector.
//   Dv[r][col] = rowlerp_uA(S)(col) - rowlerp_uB(S)(col)   (col = 0..256)
//   out = ( collerp_vA(Dv) - collerp_vB(Dv) ) / area, then BN2+ReLU+residual.
// block = (b, bt, nb, 8-row chunk); thread = column j.
// Per pixel: 4 coalesced S loads (phase 1) + 4 smem reads (phase 2) + x + out.
// ---------------------------------------------------------------------------
__global__ __launch_bounds__(256) void k3_box(
    const float* __restrict__ x,
    const float* __restrict__ xmn_, const float* __restrict__ xmx_,
    const float* __restrict__ ymn_, const float* __restrict__ ymx_,
    const float* __restrict__ g2, const float* __restrict__ b2,
    const float* __restrict__ m2, const float* __restrict__ v2,
    float* __restrict__ out)
{
    __shared__ float Dv[8][SW];     // 8 x 257 floats = 8.2 KB

    const int bid = blockIdx.x;
    const int rc  = bid & 31;                 // row chunk (8 rows)
    const int nb  = (bid >> 5) & (NBOX-1);
    const int bt  = (bid >> 7) & (BTC-1);
    const int b   = bid >> 12;
    const int j   = threadIdx.x;
    const int k   = bt*NBOX + nb;             // output channel
    const int boxi = bt*NBOX + nb;

    const float xmn = xmn_[boxi], xmx = xmx_[boxi];
    const float ymn = ymn_[boxi], ymx = ymx_[boxi];
    const float inv_area = 1.f / ((xmx - xmn) * (ymx - ymn));

    const float* Sp = g_S + (size_t)(b*BTC + bt)*SW*SW;

    // ---- phase 1: vertical lerp-difference for 8 rows, cols j (and 256) ----
    #pragma unroll
    for (int r = 0; r < 8; r++) {
        int i = rc*8 + r;
        float uA = fminf(fmaxf((float)i + xmx, 0.f), 256.f);
        float uB = fminf(fmaxf((float)i + xmn, 0.f), 256.f);
        float fA = fminf(floorf(uA), 255.f);
        float fB = fminf(floorf(uB), 255.f);
        int   iA = (int)fA, iB = (int)fB;
        float wA = uA - fA, wB = uB - fB;

        const float* RA0 = Sp + (size_t)iA*SW;
        const float* RB0 = Sp + (size_t)iB*SW;

        float d = (RA0[j]    *(1.f-wA) + RA0[SW+j]    *wA)
                - (RB0[j]    *(1.f-wB) + RB0[SW+j]    *wB);
        Dv[r][j] = d;
        if (j == 255) {
            float d2 = (RA0[256]    *(1.f-wA) + RA0[SW+256]    *wA)
                     - (RB0[256]    *(1.f-wB) + RB0[SW+256]    *wB);
            Dv[r][256] = d2;
        }
    }
    __syncthreads();

    // ---- phase 2: horizontal fractional box from smem ----
    float vA = fminf(fmaxf((float)j + ymx, 0.f), 256.f);
    float vB = fminf(fmaxf((float)j + ymn, 0.f), 256.f);
    float gA = fminf(floorf(vA), 255.f);
    float gB = fminf(floorf(vB), 255.f);
    int   jA = (int)gA, jB = (int)gB;
    float wvA = vA - gA, wvB = vB - gB;

    float inv2  = g2[k] * rsqrtf(v2[k] + 1e-3f);
    float bias2 = b2[k] - m2[k]*inv2;

    const float* xrow = x   + ((size_t)(b*CC + k)*HH + rc*8)*WW + j;
    float*       orow = out + ((size_t)(b*CC + k)*HH + rc*8)*WW + j;

    #pragma unroll
    for (int r = 0; r < 8; r++) {
        float DA = Dv[r][jA]*(1.f - wvA) + Dv[r][jA+1]*wvA;
        float DB = Dv[r][jB]*(1.f - wvB) + Dv[r][jB+1]*wvB;
        float val = (DA - DB) * inv_area;

        val = fmaxf(val*inv2 + bias2, 0.f);
        orow[(size_t)r*WW] = fmaxf(xrow[(size_t)r*WW] + val, 0.f);
    }
}

// ---------------------------------------------------------------------------
extern "C" void kernel_launch(void* const* d_in, const int* in_sizes, int n_in,
                              void* d_out, int out_size)
{
    const float* x    = (const float*)d_in[0];
    const float* w1   = (const float*)d_in[1];
    const float* g1   = (const float*)d_in[2];
    const float* b1   = (const float*)d_in[3];
    const float* m1   = (const float*)d_in[4];
    const float* v1   = (const float*)d_in[5];
    const float* xmn  = (const float*)d_in[6];
    const float* xmx  = (const float*)d_in[7];
    const float* ymn  = (const float*)d_in[8];
    const float* ymx  = (const float*)d_in[9];
    const float* g2   = (const float*)d_in[10];
    const float* b2   = (const float*)d_in[11];
    const float* m2   = (const float*)d_in[12];
    const float* v2   = (const float*)d_in[13];
    float* out = (float*)d_out;

    k1_conv_bn<<<(BB*HWSZ)/256, 256>>>(x, w1, g1, b1, m1, v1);
    k2a_colsum<<<dim3(4, BB*BTC), 256>>>();
    k2b_rowscan<<<BB*BTC*SW, 256>>>();
    k3_box<<<BB*BTC*NBOX*(HH/8), 256>>>(x, xmn, xmx, ymn, ymx, g2, b2, m2, v2, out);
}